// round 1
// baseline (speedup 1.0000x reference)
#include <cuda_runtime.h>
#include <cuda_bf16.h>
#include <cstdint>
#include <cstddef>

// Problem dims (fixed by reference)
#define TDIM 1024
#define BDIM 32
#define DIN  256
#define HDIM 256
#define AADIM 21

// Scratch (device globals: allocation-guard safe)
__device__ float g_U [ (size_t)TDIM * BDIM * 8 * HDIM ];   // 256 MB  (T,B,2,4,H)
__device__ float g_H0[ (size_t)TDIM * BDIM * 2 * HDIM ];   // 64 MB   (T,B,2H)
__device__ float g_H1[ (size_t)TDIM * BDIM * 2 * HDIM ];   // 64 MB
__device__ float g_Y [ (size_t)TDIM * BDIM * HDIM ];       // 32 MB   (T*B, H)
__device__ float g_WT[ 2 * HDIM * HDIM ];                  // fc1_w transposed (512,256)

// ---------------------------------------------------------------------------
// fp32 SIMT GEMM: C[M,N] = A[M,K] @ B[K,N] (+ bias[N])
// BM=BN=128, BK=16, 256 threads, 8x8 per thread as 4+4 split.
// XMODE: A row m maps to x[b][t] with t=m/BDIM, b=m%BDIM (x is (B,T,K)).
// ---------------------------------------------------------------------------
template<bool XMODE>
__global__ __launch_bounds__(256)
void sgemm_kernel(const float* __restrict__ A, const float* __restrict__ Bm,
                  float* __restrict__ C, int M, int N, int K,
                  const float* __restrict__ bias)
{
    __shared__ float As[16][128];
    __shared__ float Bs[16][128];

    const int tid = threadIdx.x;
    const int bm = blockIdx.y * 128;
    const int bn = blockIdx.x * 128;

    const int ty = tid >> 4;        // 0..15  -> rows ty*4, 64+ty*4
    const int tx = tid & 15;        // 0..15  -> cols tx*4, 64+tx*4

    float acc[2][2][4][4];
    #pragma unroll
    for (int p = 0; p < 2; p++)
        #pragma unroll
        for (int q = 0; q < 2; q++)
            #pragma unroll
            for (int i = 0; i < 4; i++)
                #pragma unroll
                for (int j = 0; j < 4; j++)
                    acc[p][q][i][j] = 0.f;

    const int arow  = tid >> 2;          // 0..63
    const int acol4 = (tid & 3) * 4;     // 0,4,8,12
    const int brow  = tid >> 5;          // 0..7
    const int bcol4 = (tid & 31) * 4;    // 0..124

    for (int k0 = 0; k0 < K; k0 += 16) {
        // load A tile (128 x 16), store transposed into As[k][m]
        #pragma unroll
        for (int p = 0; p < 2; p++) {
            int r  = arow + p * 64;
            int gm = bm + r;
            size_t off;
            if (XMODE) {
                int t  = gm / BDIM;
                int bb = gm % BDIM;
                off = ((size_t)bb * TDIM + t) * (size_t)K + k0 + acol4;
            } else {
                off = (size_t)gm * K + k0 + acol4;
            }
            float4 v = *(const float4*)(A + off);
            As[acol4 + 0][r] = v.x;
            As[acol4 + 1][r] = v.y;
            As[acol4 + 2][r] = v.z;
            As[acol4 + 3][r] = v.w;
        }
        // load B tile (16 x 128)
        #pragma unroll
        for (int p = 0; p < 2; p++) {
            int r = brow + p * 8;
            float4 v = *(const float4*)(Bm + (size_t)(k0 + r) * N + bn + bcol4);
            *(float4*)&Bs[r][bcol4] = v;
        }
        __syncthreads();

        #pragma unroll
        for (int kk = 0; kk < 16; kk++) {
            float4 a0 = *(const float4*)&As[kk][ty * 4];
            float4 a1 = *(const float4*)&As[kk][64 + ty * 4];
            float4 b0 = *(const float4*)&Bs[kk][tx * 4];
            float4 b1 = *(const float4*)&Bs[kk][64 + tx * 4];
            float af[2][4] = {{a0.x, a0.y, a0.z, a0.w}, {a1.x, a1.y, a1.z, a1.w}};
            float bf[2][4] = {{b0.x, b0.y, b0.z, b0.w}, {b1.x, b1.y, b1.z, b1.w}};
            #pragma unroll
            for (int p = 0; p < 2; p++)
                #pragma unroll
                for (int q = 0; q < 2; q++)
                    #pragma unroll
                    for (int i = 0; i < 4; i++)
                        #pragma unroll
                        for (int j = 0; j < 4; j++)
                            acc[p][q][i][j] += af[p][i] * bf[q][j];
        }
        __syncthreads();
    }

    // store
    #pragma unroll
    for (int p = 0; p < 2; p++) {
        #pragma unroll
        for (int i = 0; i < 4; i++) {
            int gm = bm + p * 64 + ty * 4 + i;
            #pragma unroll
            for (int q = 0; q < 2; q++) {
                int gn = bn + q * 64 + tx * 4;
                float4 v;
                v.x = acc[p][q][i][0];
                v.y = acc[p][q][i][1];
                v.z = acc[p][q][i][2];
                v.w = acc[p][q][i][3];
                if (bias) {
                    v.x += bias[gn + 0]; v.y += bias[gn + 1];
                    v.z += bias[gn + 2]; v.w += bias[gn + 3];
                }
                *(float4*)(C + (size_t)gm * N + gn) = v;
            }
        }
    }
}

// ---------------------------------------------------------------------------
// SRU scan. U layout (T,B,2,4,H): chunks [cand, forget, reset, highway].
// Hout layout (T,B,2H). One thread per (dir,b,h); 64 threads/block.
// ---------------------------------------------------------------------------
__global__ __launch_bounds__(64)
void sru_scan_kernel(const float* __restrict__ U, const float* __restrict__ wc,
                     const float* __restrict__ bvec, float* __restrict__ Hout)
{
    const int q   = HDIM / 64;                       // 4
    const int bi  = blockIdx.x;
    const int dir = bi / (BDIM * q);
    const int b   = (bi / q) % BDIM;
    const int h   = (bi % q) * 64 + threadIdx.x;

    const float vf = wc[(dir * 2 + 0) * HDIM + h];
    const float vr = wc[(dir * 2 + 1) * HDIM + h];
    const float bf = bvec[(dir * 2 + 0) * HDIM + h];
    const float br = bvec[(dir * 2 + 1) * HDIM + h];

    const int t0 = dir ? (TDIM - 1) : 0;
    const long dt = dir ? -1 : 1;

    const float* up = U + ((size_t)t0 * BDIM + b) * (8 * HDIM)
                        + (size_t)dir * 4 * HDIM + h;
    float* hp = Hout + ((size_t)t0 * BDIM + b) * (2 * HDIM)
                     + (size_t)dir * HDIM + h;
    const long ustep = dt * (long)BDIM * 8 * HDIM;
    const long hstep = dt * (long)BDIM * 2 * HDIM;

    float c = 0.f;
    float u0 = up[0], u1 = up[HDIM], u2 = up[2 * HDIM], u3 = up[3 * HDIM];

    for (int s = 0; s < TDIM; s++) {
        float n0 = 0.f, n1 = 0.f, n2 = 0.f, n3 = 0.f;
        if (s + 1 < TDIM) {
            const float* np = up + ustep;
            n0 = np[0]; n1 = np[HDIM]; n2 = np[2 * HDIM]; n3 = np[3 * HDIM];
        }
        float f  = 1.f / (1.f + __expf(-(u1 + vf * c + bf)));
        float c2 = f * c + (1.f - f) * u0;
        float r  = 1.f / (1.f + __expf(-(u2 + vr * c + br)));
        float hv = r * c2 + (1.f - r) * u3;
        c = c2;
        *hp = hv;
        up += ustep;
        hp += hstep;
        u0 = n0; u1 = n1; u2 = n2; u3 = n3;
    }
}

// ---------------------------------------------------------------------------
// Transpose fc1_w (H, 2H) -> WT (2H, H)
// ---------------------------------------------------------------------------
__global__ void transpose_fc1(const float* __restrict__ w, float* __restrict__ wt)
{
    int idx = blockIdx.x * blockDim.x + threadIdx.x;
    int total = HDIM * 2 * HDIM;
    if (idx < total) {
        int r = idx / (2 * HDIM);
        int c = idx % (2 * HDIM);
        wt[(size_t)c * HDIM + r] = w[idx];
    }
}

// ---------------------------------------------------------------------------
// logits = log_softmax(Y @ lp_w^T + lp_b). One warp per (t,b) row.
// ---------------------------------------------------------------------------
__global__ __launch_bounds__(256)
void logits_kernel(const float* __restrict__ Y, const float* __restrict__ lp_w,
                   const float* __restrict__ lp_b, float* __restrict__ out)
{
    __shared__ float ws[AADIM * HDIM];
    __shared__ float bs[32];
    const int tid = threadIdx.x;
    for (int i = tid; i < AADIM * HDIM; i += blockDim.x) ws[i] = lp_w[i];
    if (tid < AADIM) bs[tid] = lp_b[tid];
    __syncthreads();

    const int warp = tid >> 5;
    const int lane = tid & 31;
    const int row = blockIdx.x * 8 + warp;    // row = t*B + b
    const int t = row / BDIM;
    const int b = row % BDIM;

    const float* y = Y + (size_t)row * HDIM;
    float yv[8];
    #pragma unroll
    for (int i = 0; i < 8; i++) yv[i] = y[lane + 32 * i];

    float lg[AADIM];
    #pragma unroll
    for (int a = 0; a < AADIM; a++) {
        float s = 0.f;
        #pragma unroll
        for (int i = 0; i < 8; i++) s += yv[i] * ws[a * HDIM + lane + 32 * i];
        #pragma unroll
        for (int off = 16; off > 0; off >>= 1)
            s += __shfl_xor_sync(0xFFFFFFFFu, s, off);
        lg[a] = s + bs[a];
    }

    float mx = lg[0];
    #pragma unroll
    for (int a = 1; a < AADIM; a++) mx = fmaxf(mx, lg[a]);
    float se = 0.f;
    #pragma unroll
    for (int a = 0; a < AADIM; a++) se += __expf(lg[a] - mx);
    float lse = mx + __logf(se);

    float myv = 0.f;
    #pragma unroll
    for (int a = 0; a < AADIM; a++) if (lane == a) myv = lg[a] - lse;
    if (lane < AADIM)
        out[((size_t)b * TDIM + t) * AADIM + lane] = myv;
}

// ---------------------------------------------------------------------------
extern "C" void kernel_launch(void* const* d_in, const int* in_sizes, int n_in,
                              void* d_out, int out_size)
{
    const float* x     = (const float*)d_in[0];
    // d_in[1] = hidden (unused)
    const float* w_l0  = (const float*)d_in[2];
    const float* wc_l0 = (const float*)d_in[3];
    const float* b_l0  = (const float*)d_in[4];
    const float* w_l1  = (const float*)d_in[5];
    const float* wc_l1 = (const float*)d_in[6];
    const float* b_l1  = (const float*)d_in[7];
    const float* fc1_w = (const float*)d_in[8];
    const float* fc1_b = (const float*)d_in[9];
    const float* lp_w  = (const float*)d_in[10];
    const float* lp_b  = (const float*)d_in[11];
    float* out = (float*)d_out;

    float *pU, *pH0, *pH1, *pY, *pWT;
    cudaGetSymbolAddress((void**)&pU,  g_U);
    cudaGetSymbolAddress((void**)&pH0, g_H0);
    cudaGetSymbolAddress((void**)&pH1, g_H1);
    cudaGetSymbolAddress((void**)&pY,  g_Y);
    cudaGetSymbolAddress((void**)&pWT, g_WT);

    const int M = TDIM * BDIM;      // 32768

    // GEMM1: U0 = x(T,B view) @ w_l0  [32768 x 2048 x 256]
    {
        dim3 grid(2048 / 128, M / 128);
        sgemm_kernel<true><<<grid, 256>>>(x, w_l0, pU, M, 2048, DIN, nullptr);
    }
    // scan layer 0 -> H0
    sru_scan_kernel<<<2 * BDIM * (HDIM / 64), 64>>>(pU, wc_l0, b_l0, pH0);

    // GEMM2: U1 = H0 @ w_l1  [32768 x 2048 x 512]
    {
        dim3 grid(2048 / 128, M / 128);
        sgemm_kernel<false><<<grid, 256>>>(pH0, w_l1, pU, M, 2048, 2 * HDIM, nullptr);
    }
    // scan layer 1 -> H1
    sru_scan_kernel<<<2 * BDIM * (HDIM / 64), 64>>>(pU, wc_l1, b_l1, pH1);

    // transpose fc1_w -> WT (2H, H)
    transpose_fc1<<<(HDIM * 2 * HDIM + 255) / 256, 256>>>(fc1_w, pWT);

    // GEMM3: Y = H1 @ WT + fc1_b  [32768 x 256 x 512]
    {
        dim3 grid(HDIM / 128, M / 128);
        sgemm_kernel<false><<<grid, 256>>>(pH1, pWT, pY, M, HDIM, 2 * HDIM, fc1_b);
    }

    // logits + log_softmax
    logits_kernel<<<M / 8, 256>>>(pY, lp_w, lp_b, out);
}

// round 2
// speedup vs baseline: 2.3641x; 2.3641x over previous
#include <cuda_runtime.h>
#include <cuda_bf16.h>
#include <cstdint>
#include <cstddef>

// Problem dims (fixed by reference)
#define TDIM 1024
#define BDIM 32
#define DIN  256
#define HDIM 256
#define AADIM 21

// Scratch (device globals: allocation-guard safe)
__device__ float g_U [ (size_t)TDIM * BDIM * 8 * HDIM ];   // 256 MB  (T,B,2,4,H)
__device__ float g_H0[ (size_t)TDIM * BDIM * 2 * HDIM ];   // 64 MB   (T,B,2H)
__device__ float g_H1[ (size_t)TDIM * BDIM * 2 * HDIM ];   // 64 MB
__device__ float g_Y [ (size_t)TDIM * BDIM * HDIM ];       // 32 MB   (T*B, H)
__device__ float g_WT[ 2 * HDIM * HDIM ];                  // fc1_w transposed (512,256)

__device__ __forceinline__ uint32_t f2tf(float f) {
    uint32_t u;
    asm("cvt.rna.tf32.f32 %0, %1;" : "=r"(u) : "f"(f));
    return u;
}

// ---------------------------------------------------------------------------
// TF32 tensor-core GEMM: C[M,N] = A[M,K] @ B[K,N] (+bias).
// BM=BN=128, BK=32. 256 threads = 8 warps, warp tile 64x32 (warps 2x4).
// mma.sync.m16n8k8.tf32. XMODE: A row m -> x[b][t], t=m/B, b=m%B.
// ---------------------------------------------------------------------------
#define LDA 137
#define LDB 136

template<bool XMODE>
__global__ __launch_bounds__(256)
void tf32_gemm(const float* __restrict__ A, const float* __restrict__ Bm,
               float* __restrict__ C, int M, int N, int K,
               const float* __restrict__ bias)
{
    __shared__ uint32_t As[32 * LDA];   // [k][m]
    __shared__ uint32_t Bs[32 * LDB];   // [k][n]

    const int tid  = threadIdx.x;
    const int lane = tid & 31;
    const int wid  = tid >> 5;
    const int bm = blockIdx.y * 128;
    const int bn = blockIdx.x * 128;
    const int wm = (wid & 1) * 64;
    const int wn = (wid >> 1) * 32;

    float acc[4][4][4];
    #pragma unroll
    for (int mi = 0; mi < 4; mi++)
        #pragma unroll
        for (int ni = 0; ni < 4; ni++)
            #pragma unroll
            for (int r = 0; r < 4; r++)
                acc[mi][ni][r] = 0.f;

    // A-load indexing: 128 rows x 32 k; each thread 4 float4 along K
    const int ar0 = tid >> 3;          // 0..31  (rows ar0, +32, +64, +96)
    const int akq = (tid & 7) * 4;     // 0..28
    // B-load indexing: 32 k-rows x 128 n; each thread 4 float4 along N
    const int bkr = tid >> 5;          // 0..7   (k-rows bkr, +8, +16, +24)
    const int bnc = (tid & 31) * 4;    // 0..124

    const int g2 = lane >> 2;          // 0..7
    const int g4 = lane & 3;           // 0..3

    for (int k0 = 0; k0 < K; k0 += 32) {
        // ---- load A tile, transposed into As[k][m], cvt to tf32
        #pragma unroll
        for (int p = 0; p < 4; p++) {
            int r  = ar0 + p * 32;
            int gm = bm + r;
            size_t off;
            if (XMODE) {
                int t  = gm / BDIM;
                int bb = gm % BDIM;
                off = ((size_t)bb * TDIM + t) * (size_t)K + k0 + akq;
            } else {
                off = (size_t)gm * K + k0 + akq;
            }
            float4 v = *(const float4*)(A + off);
            As[(akq + 0) * LDA + r] = f2tf(v.x);
            As[(akq + 1) * LDA + r] = f2tf(v.y);
            As[(akq + 2) * LDA + r] = f2tf(v.z);
            As[(akq + 3) * LDA + r] = f2tf(v.w);
        }
        // ---- load B tile into Bs[k][n]
        #pragma unroll
        for (int p = 0; p < 4; p++) {
            int kr = bkr + p * 8;
            float4 v = *(const float4*)(Bm + (size_t)(k0 + kr) * N + bn + bnc);
            Bs[kr * LDB + bnc + 0] = f2tf(v.x);
            Bs[kr * LDB + bnc + 1] = f2tf(v.y);
            Bs[kr * LDB + bnc + 2] = f2tf(v.z);
            Bs[kr * LDB + bnc + 3] = f2tf(v.w);
        }
        __syncthreads();

        #pragma unroll
        for (int kk = 0; kk < 4; kk++) {
            const int kb = kk * 8;
            uint32_t af[4][4], bfr[4][2];
            #pragma unroll
            for (int mi = 0; mi < 4; mi++) {
                int r = wm + mi * 16 + g2;
                af[mi][0] = As[(kb + g4) * LDA + r];
                af[mi][1] = As[(kb + g4) * LDA + r + 8];
                af[mi][2] = As[(kb + g4 + 4) * LDA + r];
                af[mi][3] = As[(kb + g4 + 4) * LDA + r + 8];
            }
            #pragma unroll
            for (int ni = 0; ni < 4; ni++) {
                int cn = wn + ni * 8 + g2;
                bfr[ni][0] = Bs[(kb + g4) * LDB + cn];
                bfr[ni][1] = Bs[(kb + g4 + 4) * LDB + cn];
            }
            #pragma unroll
            for (int mi = 0; mi < 4; mi++)
                #pragma unroll
                for (int ni = 0; ni < 4; ni++) {
                    asm volatile(
                        "mma.sync.aligned.m16n8k8.row.col.f32.tf32.tf32.f32 "
                        "{%0,%1,%2,%3}, {%4,%5,%6,%7}, {%8,%9}, {%0,%1,%2,%3};"
                        : "+f"(acc[mi][ni][0]), "+f"(acc[mi][ni][1]),
                          "+f"(acc[mi][ni][2]), "+f"(acc[mi][ni][3])
                        : "r"(af[mi][0]), "r"(af[mi][1]),
                          "r"(af[mi][2]), "r"(af[mi][3]),
                          "r"(bfr[ni][0]), "r"(bfr[ni][1]));
                }
        }
        __syncthreads();
    }

    // ---- store C (+bias). c0,c1 at cols 2*g4, 2*g4+1; c2,c3 at row+8.
    #pragma unroll
    for (int mi = 0; mi < 4; mi++) {
        int row0 = bm + wm + mi * 16 + g2;
        #pragma unroll
        for (int ni = 0; ni < 4; ni++) {
            int col = bn + wn + ni * 8 + 2 * g4;
            float bx = 0.f, by = 0.f;
            if (bias) { bx = bias[col]; by = bias[col + 1]; }
            float2 v0 = make_float2(acc[mi][ni][0] + bx, acc[mi][ni][1] + by);
            float2 v1 = make_float2(acc[mi][ni][2] + bx, acc[mi][ni][3] + by);
            *(float2*)(C + (size_t)row0 * N + col)       = v0;
            *(float2*)(C + (size_t)(row0 + 8) * N + col) = v1;
        }
    }
}

// ---------------------------------------------------------------------------
// SRU scan with depth-8 register ring-buffer prefetch.
// U layout (T,B,2,4,H): chunks [cand, forget, reset, highway].
// Hout layout (T,B,2H). One thread per (dir,b,h); 64 threads/block.
// ---------------------------------------------------------------------------
#define SCAN_D 8

__global__ __launch_bounds__(64)
void sru_scan_kernel(const float* __restrict__ U, const float* __restrict__ wc,
                     const float* __restrict__ bvec, float* __restrict__ Hout)
{
    const int q   = HDIM / 64;                       // 4
    const int bi  = blockIdx.x;
    const int dir = bi / (BDIM * q);
    const int b   = (bi / q) % BDIM;
    const int h   = (bi % q) * 64 + threadIdx.x;

    const float vf = wc[(dir * 2 + 0) * HDIM + h];
    const float vr = wc[(dir * 2 + 1) * HDIM + h];
    const float bf = bvec[(dir * 2 + 0) * HDIM + h];
    const float br = bvec[(dir * 2 + 1) * HDIM + h];

    const int t0 = dir ? (TDIM - 1) : 0;
    const long dt = dir ? -1 : 1;

    const float* up = U + ((size_t)t0 * BDIM + b) * (8 * HDIM)
                        + (size_t)dir * 4 * HDIM + h;
    float* hp = Hout + ((size_t)t0 * BDIM + b) * (2 * HDIM)
                     + (size_t)dir * HDIM + h;
    const long ustep = dt * (long)BDIM * 8 * HDIM;
    const long hstep = dt * (long)BDIM * 2 * HDIM;

    float r0[SCAN_D], r1[SCAN_D], r2[SCAN_D], r3[SCAN_D];
    const float* lp = up;
    #pragma unroll
    for (int d = 0; d < SCAN_D; d++) {
        r0[d] = lp[0]; r1[d] = lp[HDIM];
        r2[d] = lp[2 * HDIM]; r3[d] = lp[3 * HDIM];
        lp += ustep;
    }

    float c = 0.f;
    for (int s0 = 0; s0 < TDIM; s0 += SCAN_D) {
        #pragma unroll
        for (int d = 0; d < SCAN_D; d++) {
            float u0 = r0[d], u1 = r1[d], u2 = r2[d], u3 = r3[d];
            // refill this slot with step s0+d+SCAN_D
            if (s0 + d + SCAN_D < TDIM) {
                r0[d] = lp[0]; r1[d] = lp[HDIM];
                r2[d] = lp[2 * HDIM]; r3[d] = lp[3 * HDIM];
                lp += ustep;
            }
            float f  = 1.f / (1.f + __expf(-(u1 + vf * c + bf)));
            float c2 = f * c + (1.f - f) * u0;
            float r  = 1.f / (1.f + __expf(-(u2 + vr * c + br)));
            float hv = r * c2 + (1.f - r) * u3;
            c = c2;
            *hp = hv;
            hp += hstep;
        }
    }
}

// ---------------------------------------------------------------------------
// Transpose fc1_w (H, 2H) -> WT (2H, H)
// ---------------------------------------------------------------------------
__global__ void transpose_fc1(const float* __restrict__ w, float* __restrict__ wt)
{
    int idx = blockIdx.x * blockDim.x + threadIdx.x;
    int total = HDIM * 2 * HDIM;
    if (idx < total) {
        int r = idx / (2 * HDIM);
        int c = idx % (2 * HDIM);
        wt[(size_t)c * HDIM + r] = w[idx];
    }
}

// ---------------------------------------------------------------------------
// logits = log_softmax(Y @ lp_w^T + lp_b). One warp per (t,b) row.
// ---------------------------------------------------------------------------
__global__ __launch_bounds__(256)
void logits_kernel(const float* __restrict__ Y, const float* __restrict__ lp_w,
                   const float* __restrict__ lp_b, float* __restrict__ out)
{
    __shared__ float ws[AADIM * HDIM];
    __shared__ float bs[32];
    const int tid = threadIdx.x;
    for (int i = tid; i < AADIM * HDIM; i += blockDim.x) ws[i] = lp_w[i];
    if (tid < AADIM) bs[tid] = lp_b[tid];
    __syncthreads();

    const int warp = tid >> 5;
    const int lane = tid & 31;
    const int row = blockIdx.x * 8 + warp;    // row = t*B + b
    const int t = row / BDIM;
    const int b = row % BDIM;

    const float* y = Y + (size_t)row * HDIM;
    float yv[8];
    #pragma unroll
    for (int i = 0; i < 8; i++) yv[i] = y[lane + 32 * i];

    float lg[AADIM];
    #pragma unroll
    for (int a = 0; a < AADIM; a++) {
        float s = 0.f;
        #pragma unroll
        for (int i = 0; i < 8; i++) s += yv[i] * ws[a * HDIM + lane + 32 * i];
        #pragma unroll
        for (int off = 16; off > 0; off >>= 1)
            s += __shfl_xor_sync(0xFFFFFFFFu, s, off);
        lg[a] = s + bs[a];
    }

    float mx = lg[0];
    #pragma unroll
    for (int a = 1; a < AADIM; a++) mx = fmaxf(mx, lg[a]);
    float se = 0.f;
    #pragma unroll
    for (int a = 0; a < AADIM; a++) se += __expf(lg[a] - mx);
    float lse = mx + __logf(se);

    float myv = 0.f;
    #pragma unroll
    for (int a = 0; a < AADIM; a++) if (lane == a) myv = lg[a] - lse;
    if (lane < AADIM)
        out[((size_t)b * TDIM + t) * AADIM + lane] = myv;
}

// ---------------------------------------------------------------------------
extern "C" void kernel_launch(void* const* d_in, const int* in_sizes, int n_in,
                              void* d_out, int out_size)
{
    const float* x     = (const float*)d_in[0];
    // d_in[1] = hidden (unused)
    const float* w_l0  = (const float*)d_in[2];
    const float* wc_l0 = (const float*)d_in[3];
    const float* b_l0  = (const float*)d_in[4];
    const float* w_l1  = (const float*)d_in[5];
    const float* wc_l1 = (const float*)d_in[6];
    const float* b_l1  = (const float*)d_in[7];
    const float* fc1_w = (const float*)d_in[8];
    const float* fc1_b = (const float*)d_in[9];
    const float* lp_w  = (const float*)d_in[10];
    const float* lp_b  = (const float*)d_in[11];
    float* out = (float*)d_out;

    float *pU, *pH0, *pH1, *pY, *pWT;
    cudaGetSymbolAddress((void**)&pU,  g_U);
    cudaGetSymbolAddress((void**)&pH0, g_H0);
    cudaGetSymbolAddress((void**)&pH1, g_H1);
    cudaGetSymbolAddress((void**)&pY,  g_Y);
    cudaGetSymbolAddress((void**)&pWT, g_WT);

    const int M = TDIM * BDIM;      // 32768

    // GEMM1: U0 = x(T,B view) @ w_l0  [32768 x 2048 x 256]
    {
        dim3 grid(2048 / 128, M / 128);
        tf32_gemm<true><<<grid, 256>>>(x, w_l0, pU, M, 2048, DIN, nullptr);
    }
    // scan layer 0 -> H0
    sru_scan_kernel<<<2 * BDIM * (HDIM / 64), 64>>>(pU, wc_l0, b_l0, pH0);

    // GEMM2: U1 = H0 @ w_l1  [32768 x 2048 x 512]
    {
        dim3 grid(2048 / 128, M / 128);
        tf32_gemm<false><<<grid, 256>>>(pH0, w_l1, pU, M, 2048, 2 * HDIM, nullptr);
    }
    // scan layer 1 -> H1
    sru_scan_kernel<<<2 * BDIM * (HDIM / 64), 64>>>(pU, wc_l1, b_l1, pH1);

    // transpose fc1_w -> WT (2H, H)
    transpose_fc1<<<(HDIM * 2 * HDIM + 255) / 256, 256>>>(fc1_w, pWT);

    // GEMM3: Y = H1 @ WT + fc1_b  [32768 x 256 x 512]
    {
        dim3 grid(HDIM / 128, M / 128);
        tf32_gemm<false><<<grid, 256>>>(pH1, pWT, pY, M, HDIM, 2 * HDIM, fc1_b);
    }

    // logits + log_softmax
    logits_kernel<<<M / 8, 256>>>(pY, lp_w, lp_b, out);
}